// round 4
// baseline (speedup 1.0000x reference)
#include <cuda_runtime.h>
#include <math.h>

#define TT 4096
#define BB 128
#define HH 256
#define MAXSEG (BB*(TT/5))   /* 104832 */
#define PI_F 3.14159265358979323846f

// ---------------- scratch (static __device__, no allocations) ----------------
__device__ float g_rot[(size_t)BB*TT*3];            // rotated trajectory
__device__ float g_ar[(size_t)MAXSEG*HH];           // ar_in  [N,256]
__device__ float g_gx[(size_t)MAXSEG*3*HH];         // x @ W_ih^T + b_ih  [N,768]
__device__ float g_h[2][BB*HH];                     // GRU hidden, double buffered
__device__ int   g_segs[BB];
__device__ int   g_rr[BB];
__device__ int   g_offs[BB+1];
__device__ float g_ox[BB], g_oy[BB], g_hd[BB], g_c[BB], g_s[BB];
__device__ int   g_total, g_smax;
__device__ unsigned g_barA = 0, g_barR = 0;

// ---------------- kernel 0: per-batch bookkeeping -----------------------------
__global__ void k_setup(const float* __restrict__ traj, const int* __restrict__ len)
{
    int b = threadIdx.x;          // 128 threads
    __shared__ int ss[BB];
    if (b < BB) {
        int L = len[b];
        int sg = L / 5;
        g_segs[b] = sg;
        g_rr[b]   = L % 5;
        ss[b] = sg;
        const float* last = traj + ((size_t)b*TT + (size_t)(L-1))*3;
        float ox = last[0], oy = last[1], hd = -last[2];
        g_ox[b] = ox; g_oy[b] = oy; g_hd[b] = hd;
        float th = hd * (PI_F/180.0f);
        g_c[b] = cosf(th); g_s[b] = sinf(th);
    }
    __syncthreads();
    if (b == 0) {
        int acc = 0, mx = 0;
        for (int i = 0; i < BB; i++) { g_offs[i] = acc; acc += ss[i]; if (ss[i] > mx) mx = ss[i]; }
        g_offs[BB] = acc;
        g_total = acc;
        g_smax  = mx;
    }
    for (int i = b; i < BB*HH; i += blockDim.x) g_h[0][i] = 0.0f;   // h0 = 0
}

// ---------------- kernel 1: rotate whole trajectory ---------------------------
__global__ void k_rot(const float* __restrict__ traj)
{
    int i = blockIdx.x*blockDim.x + threadIdx.x;
    const int tot = BB*TT;
    for (; i < tot; i += gridDim.x*blockDim.x) {
        int b = i >> 12;                 // T = 4096
        size_t base = (size_t)i*3;
        float x = traj[base], y = traj[base+1], a = traj[base+2];
        float dx = x - g_ox[b], dy = y - g_oy[b];
        float c = g_c[b], s = g_s[b];
        g_rot[base]   = c*dx - s*dy;
        g_rot[base+1] = s*dx + c*dy;
        float aa = fmodf(a + g_hd[b] + 720.0f, 360.0f) * (PI_F/180.0f);
        if (aa > PI_F) aa -= 2.0f*PI_F;
        g_rot[base+2] = aa;
    }
}

// ---------------- kernel 2: conv1 -> conv2 -> mean  => ar_in ------------------
#define OCG  32
#define SEGC 8
__global__ __launch_bounds__(256,1) void k_conv(const float* __restrict__ w1,
                                                const float* __restrict__ b1,
                                                const float* __restrict__ w2,
                                                const float* __restrict__ b2)
{
    extern __shared__ float sm[];
    float* sW2 = sm;                       // 32*769
    float* sY  = sW2 + OCG*769;            // 8*256*7   (y1 padded: slots 0..6 = t=-1..5)
    float* sW1 = sY + SEGC*HH*7;           // 2304
    float* sB1 = sW1 + 2304;               // 256
    float* sB2 = sB1 + 256;                // 32
    float* sR  = sB2 + OCG;                // 120
    __shared__ int sOffs[BB+1];
    __shared__ int sBi[SEGC], sT0[SEGC];

    const int tid = threadIdx.x;
    const int ocb = blockIdx.x * OCG;

    for (int idx = tid; idx < OCG*768; idx += 256) {
        int oc = idx / 768, k = idx - oc*768;
        sW2[oc*769 + k] = w2[(size_t)(ocb+oc)*768 + k];
    }
    for (int idx = tid; idx < 2304; idx += 256) sW1[idx] = w1[idx];
    sB1[tid] = b1[tid];
    if (tid < OCG) sB2[tid] = b2[ocb + tid];
    for (int idx = tid; idx <= BB; idx += 256) sOffs[idx] = g_offs[idx];
    __syncthreads();

    const int total   = g_total;
    const int nchunks = (total + SEGC - 1) / SEGC;

    for (int c = blockIdx.y; c < nchunks; c += gridDim.y) {
        const int base = c * SEGC;
        const int cnt  = min(SEGC, total - base);

        if (tid < cnt) {                              // segment -> (b,k) -> t0
            int n = base + tid;
            int lo = 0, hi = BB;
            while (hi - lo > 1) { int mid = (lo+hi) >> 1; if (sOffs[mid] <= n) lo = mid; else hi = mid; }
            int k = n - sOffs[lo];
            sBi[tid] = lo;
            sT0[tid] = g_rr[lo] + 5*k;
        }
        __syncthreads();
        if (tid < cnt*15) {                           // stage 5x3 rotated points / seg
            int s = tid / 15, e = tid - s*15;
            sR[s*15 + e] = g_rot[((size_t)sBi[s]*TT + (size_t)sT0[s])*3 + e];
        }
        __syncthreads();

        // conv1: thread = channel
        {
            const int ch = tid;
            float w[9];
            #pragma unroll
            for (int i = 0; i < 9; i++) w[i] = sW1[ch*9 + i];
            const float bb = sB1[ch];
            for (int s = 0; s < cnt; s++) {
                float* yb = sY + (s*HH + ch)*7;
                yb[0] = 0.0f; yb[6] = 0.0f;
                const float* xr = sR + s*15;
                #pragma unroll
                for (int p = 0; p < 5; p++) {
                    float acc = bb;
                    #pragma unroll
                    for (int dt = 0; dt < 3; dt++) {
                        int t = p + dt - 1;
                        if (t >= 0 && t < 5)
                            acc += w[0*3+dt]*xr[t*3+0] + w[1*3+dt]*xr[t*3+1] + w[2*3+dt]*xr[t*3+2];
                    }
                    yb[1+p] = fmaxf(acc, 0.0f);
                }
            }
        }
        __syncthreads();

        // conv2 + relu + mean: thread = (segment s, out-channel oc)
        {
            const int s  = tid >> 5;
            const int oc = tid & 31;
            if (s < cnt) {
                float bb = sB2[oc];
                float acc0=bb, acc1=bb, acc2=bb, acc3=bb, acc4=bb;
                const float* wrow = sW2 + oc*769;
                const float* yrow = sY + s*HH*7;
                #pragma unroll 4
                for (int j = 0; j < HH; j++) {
                    float w0 = wrow[j*3], w1v = wrow[j*3+1], w2v = wrow[j*3+2];
                    const float* yj = yrow + j*7;
                    float a0=yj[0],a1=yj[1],a2=yj[2],a3=yj[3],a4=yj[4],a5=yj[5],a6=yj[6];
                    acc0 += w0*a0 + w1v*a1 + w2v*a2;
                    acc1 += w0*a1 + w1v*a2 + w2v*a3;
                    acc2 += w0*a2 + w1v*a3 + w2v*a4;
                    acc3 += w0*a3 + w1v*a4 + w2v*a5;
                    acc4 += w0*a4 + w1v*a5 + w2v*a6;
                }
                float m = fmaxf(acc0,0.f)+fmaxf(acc1,0.f)+fmaxf(acc2,0.f)
                        + fmaxf(acc3,0.f)+fmaxf(acc4,0.f);
                g_ar[(size_t)(base+s)*HH + ocb + oc] = m * 0.2f;
            }
        }
        __syncthreads();
    }
}

// ---------------- kernel 3: gx = ar_in @ W_ih^T + b_ih  [N,768] ---------------
__global__ __launch_bounds__(256) void k_gx(const float* __restrict__ wih,
                                            const float* __restrict__ bih)
{
    __shared__ float As[64*33];
    __shared__ float Bs[64*33];
    const int total = g_total;
    const int m0 = blockIdx.x * 64;
    if (m0 >= total) return;
    const int g0 = blockIdx.y * 64;
    const int tid = threadIdx.x;
    const int tr = (tid >> 4) * 4;
    const int tc = (tid & 15) * 4;
    float acc[4][4] = {};

    for (int kc = 0; kc < HH; kc += 32) {
        for (int idx = tid; idx < 64*32; idx += 256) {
            int r = idx >> 5, kk = idx & 31;
            int m = m0 + r;
            As[r*33 + kk] = (m < total) ? g_ar[(size_t)m*HH + kc + kk] : 0.0f;
        }
        for (int idx = tid; idx < 64*32; idx += 256) {
            int g = idx >> 5, kk = idx & 31;
            Bs[g*33 + kk] = wih[(size_t)(g0+g)*HH + kc + kk];
        }
        __syncthreads();
        #pragma unroll
        for (int kk = 0; kk < 32; kk++) {
            float a[4], bv[4];
            #pragma unroll
            for (int i = 0; i < 4; i++) a[i]  = As[(tr+i)*33 + kk];
            #pragma unroll
            for (int j = 0; j < 4; j++) bv[j] = Bs[(tc+j)*33 + kk];
            #pragma unroll
            for (int i = 0; i < 4; i++)
                #pragma unroll
                for (int j = 0; j < 4; j++)
                    acc[i][j] += a[i]*bv[j];
        }
        __syncthreads();
    }
    float bi[4];
    #pragma unroll
    for (int j = 0; j < 4; j++) bi[j] = bih[g0 + tc + j];
    #pragma unroll
    for (int i = 0; i < 4; i++) {
        int m = m0 + tr + i;
        if (m < total) {
            #pragma unroll
            for (int j = 0; j < 4; j++)
                g_gx[(size_t)m*768 + g0 + tc + j] = acc[i][j] + bi[j];
        }
    }
}

// ---------------- kernel 4: persistent GRU over segments ----------------------
#define NBLK 128
#define BG 16    // samples per block
#define UG 16    // hidden units per block
__device__ __forceinline__ void gridbar()
{
    __syncthreads();
    if (threadIdx.x == 0) {
        __threadfence();
        unsigned t = atomicAdd(&g_barA, 1u);
        unsigned gen = t / (unsigned)NBLK + 1u;
        if ((t % (unsigned)NBLK) == (unsigned)NBLK - 1u) {
            atomicExch(&g_barR, gen);
        } else {
            while (*((volatile unsigned*)&g_barR) < gen) { }
        }
    }
    __syncthreads();
}

__global__ __launch_bounds__(128,1) void k_gru(const float* __restrict__ whh,
                                               const float* __restrict__ bhh,
                                               float* __restrict__ out)
{
    extern __shared__ float sm[];
    float* sW = sm;              // 48*257 : rows 0..15=r, 16..31=z, 32..47=n
    float* sh = sm + 48*257;     // 16*257 : staged h for this block's 16 samples

    const int tid = threadIdx.x;
    const int bg  = blockIdx.x & 7;
    const int ug  = blockIdx.x >> 3;

    for (int idx = tid; idx < 48*256; idx += 128) {
        int lr = idx >> 8, col = idx & 255;
        int gate = lr >> 4, uu = lr & 15;
        int grow = gate*HH + ug*UG + uu;
        sW[lr*257 + col] = whh[(size_t)grow*HH + col];
    }

    const int sp = tid >> 4;             // 0..7  -> samples 2sp, 2sp+1
    const int ui = tid & 15;
    const int u  = ug*UG + ui;
    const float bhr = bhh[u], bhz = bhh[HH+u], bhn = bhh[2*HH+u];
    const int b0 = bg*BG + 2*sp, b1v = b0 + 1;
    const int seg0 = g_segs[b0], seg1 = g_segs[b1v];
    const int off0 = g_offs[b0], off1 = g_offs[b1v];
    const int smax = g_smax;

    for (int k = 0; k < smax; k++) {
        const int cur = k & 1, nxt = cur ^ 1;
        gridbar();                                   // prev step's h writes visible
        for (int idx = tid; idx < BG*HH; idx += 128) {
            int si = idx >> 8, col = idx & 255;
            sh[si*257 + col] = __ldcg(&g_h[cur][(bg*BG + si)*HH + col]);
        }
        __syncthreads();

        float ar0=0.f, az0=0.f, an0=0.f, ar1=0.f, az1=0.f, an1=0.f;
        const float* wr  = sW + ui*257;
        const float* wz  = sW + (16+ui)*257;
        const float* wn  = sW + (32+ui)*257;
        const float* h0p = sh + (2*sp)*257;
        const float* h1p = sh + (2*sp+1)*257;
        #pragma unroll 8
        for (int kk = 0; kk < HH; kk++) {
            float h0 = h0p[kk], h1 = h1p[kk];
            float w_r = wr[kk], w_z = wz[kk], w_n = wn[kk];
            ar0 += h0*w_r; az0 += h0*w_z; an0 += h0*w_n;
            ar1 += h1*w_r; az1 += h1*w_z; an1 += h1*w_n;
        }

        {   // sample 0
            float hold = h0p[u], hnew;
            if (k < seg0) {
                size_t row = (size_t)(off0 + k);
                float gxr = g_gx[row*768 + u];
                float gxz = g_gx[row*768 + HH + u];
                float gxn = g_gx[row*768 + 2*HH + u];
                float r = 1.0f/(1.0f + expf(-(gxr + ar0 + bhr)));
                float z = 1.0f/(1.0f + expf(-(gxz + az0 + bhz)));
                float n = tanhf(gxn + r*(an0 + bhn));
                hnew = (1.0f - z)*n + z*hold;
                out[row*HH + u] = hnew;
            } else hnew = hold;
            __stcg(&g_h[nxt][b0*HH + u], hnew);
        }
        {   // sample 1
            float hold = h1p[u], hnew;
            if (k < seg1) {
                size_t row = (size_t)(off1 + k);
                float gxr = g_gx[row*768 + u];
                float gxz = g_gx[row*768 + HH + u];
                float gxn = g_gx[row*768 + 2*HH + u];
                float r = 1.0f/(1.0f + expf(-(gxr + ar1 + bhr)));
                float z = 1.0f/(1.0f + expf(-(gxz + az1 + bhz)));
                float n = tanhf(gxn + r*(an1 + bhn));
                hnew = (1.0f - z)*n + z*hold;
                out[row*HH + u] = hnew;
            } else hnew = hold;
            __stcg(&g_h[nxt][b1v*HH + u], hnew);
        }
    }
}

// ---------------- launch ------------------------------------------------------
extern "C" void kernel_launch(void* const* d_in, const int* in_sizes, int n_in,
                              void* d_out, int out_size)
{
    const float* traj = (const float*)d_in[0];
    const int*   len  = (const int*)  d_in[1];
    const float* c1w  = (const float*)d_in[2];
    const float* c1b  = (const float*)d_in[3];
    const float* c2w  = (const float*)d_in[4];
    const float* c2b  = (const float*)d_in[5];
    const float* wih  = (const float*)d_in[6];
    const float* whh  = (const float*)d_in[7];
    const float* bih  = (const float*)d_in[8];
    const float* bhh  = (const float*)d_in[9];
    float* out = (float*)d_out;

    const int conv_smem = (OCG*769 + SEGC*HH*7 + 2304 + 256 + OCG + 120) * 4;
    const int gru_smem  = (48*257 + 16*257) * 4;
    cudaFuncSetAttribute(k_conv, cudaFuncAttributeMaxDynamicSharedMemorySize, conv_smem);
    cudaFuncSetAttribute(k_gru,  cudaFuncAttributeMaxDynamicSharedMemorySize, gru_smem);

    k_setup<<<1, 128>>>(traj, len);
    k_rot<<<512, 256>>>(traj);
    k_conv<<<dim3(8, 18), 256, conv_smem>>>(c1w, c1b, c2w, c2b);
    k_gx<<<dim3((MAXSEG + 63) / 64, 12), 256>>>(wih, bih);
    k_gru<<<NBLK, 128, gru_smem>>>(whh, bhh, out);
}

// round 5
// speedup vs baseline: 1.0146x; 1.0146x over previous
#include <cuda_runtime.h>
#include <math.h>

#define TT 4096
#define BB 128
#define HH 256
#define MAXSEG (BB*(TT/5))
#define PI_F 3.14159265358979323846f

typedef unsigned long long u64;
__device__ __forceinline__ u64 pk2(float lo, float hi){ u64 r; asm("mov.b64 %0,{%1,%2};":"=l"(r):"f"(lo),"f"(hi)); return r; }
__device__ __forceinline__ void up2(u64 v, float& lo, float& hi){ asm("mov.b64 {%0,%1},%2;":"=f"(lo),"=f"(hi):"l"(v)); }
__device__ __forceinline__ void fma2(u64& d, u64 a, u64 b){ asm("fma.rn.f32x2 %0,%1,%2,%0;":"+l"(d):"l"(a),"l"(b)); }

// ---------------- scratch ----------------
__device__ float g_rot[(size_t)BB*TT*3];
__device__ float g_ar[(size_t)MAXSEG*HH];
__device__ float g_gx[(size_t)MAXSEG*3*HH];
__device__ u64   g_h[2][(BB/2)*HH];          // sample-pair interleaved: [pair][unit] -> (h_even,h_odd)
__device__ int   g_segs[BB], g_rr[BB], g_offs[BB+1];
__device__ float g_ox[BB], g_oy[BB], g_hd[BB], g_c[BB], g_s[BB];
__device__ int   g_total, g_gmax[8];
__device__ unsigned g_barA[8*32], g_barR[8*32];   // padded, one pair per sample-group

// ---------------- kernel 0: setup ----------------
__global__ void k_setup(const float* __restrict__ traj, const int* __restrict__ len)
{
    int b = threadIdx.x;
    __shared__ int ss[BB];
    if (b < BB) {
        int L = len[b];
        g_segs[b] = L/5; g_rr[b] = L%5; ss[b] = L/5;
        const float* last = traj + ((size_t)b*TT + (size_t)(L-1))*3;
        g_ox[b]=last[0]; g_oy[b]=last[1]; float hd=-last[2]; g_hd[b]=hd;
        float th = hd*(PI_F/180.0f);
        g_c[b]=cosf(th); g_s[b]=sinf(th);
    }
    __syncthreads();
    if (b == 0) {
        int acc=0;
        for (int i=0;i<BB;i++){ g_offs[i]=acc; acc+=ss[i]; }
        g_offs[BB]=acc; g_total=acc;
        for (int g=0; g<8; g++){
            int mx=0;
            for (int i=0;i<16;i++) if (ss[g*16+i]>mx) mx=ss[g*16+i];
            g_gmax[g]=mx;
        }
    }
    for (int i=b; i<(BB/2)*HH; i+=blockDim.x) g_h[0][i]=0ull;
}

// ---------------- kernel 1: rotate ----------------
__global__ void k_rot(const float* __restrict__ traj)
{
    int i = blockIdx.x*blockDim.x + threadIdx.x;
    const int tot = BB*TT;
    for (; i<tot; i += gridDim.x*blockDim.x) {
        int b = i >> 12;
        size_t base = (size_t)i*3;
        float x=traj[base], y=traj[base+1], a=traj[base+2];
        float dx=x-g_ox[b], dy=y-g_oy[b], c=g_c[b], s=g_s[b];
        g_rot[base]   = c*dx - s*dy;
        g_rot[base+1] = s*dx + c*dy;
        float aa = fmodf(a + g_hd[b] + 720.0f, 360.0f) * (PI_F/180.0f);
        if (aa > PI_F) aa -= 2.0f*PI_F;
        g_rot[base+2] = aa;
    }
}

// ---------------- kernel 2: conv1+conv2+mean (FFMA2) ----------------
#define OCG 32          /* 16 oc pairs */
#define SEGC 12
#define CTHR 192
#define YSLAB (HH*8+4)  /* 2052 floats per segment slab (pad kills cross-seg bank conflict) */
__global__ __launch_bounds__(CTHR,1) void k_conv(const float* __restrict__ w1,
                                                 const float* __restrict__ b1,
                                                 const float* __restrict__ w2,
                                                 const float* __restrict__ b2)
{
    extern __shared__ float sm[];
    float* sW2f = sm;                       // 768*16 float2 = 24576 floats
    float* sY   = sW2f + 768*16*2;          // SEGC*2052
    float* sW1  = sY + SEGC*YSLAB;          // 2304
    float* sB1  = sW1 + 2304;               // 256
    float* sB2  = sB1 + 256;                // 16 float2 = 32
    float* sR   = sB2 + 32;                 // 180
    u64* sW2 = (u64*)sW2f;
    __shared__ int sOffs[BB+1];
    __shared__ int sBi[SEGC], sT0[SEGC];

    const int tid = threadIdx.x;
    const int ocb = blockIdx.x * OCG;

    for (int idx=tid; idx<768*16; idx+=CTHR) {
        int k = idx>>4, ocp = idx&15;
        int oc0 = ocb + 2*ocp;
        sW2[idx] = pk2(w2[(size_t)oc0*768 + k], w2[(size_t)(oc0+1)*768 + k]);
    }
    for (int idx=tid; idx<2304; idx+=CTHR) sW1[idx]=w1[idx];
    for (int idx=tid; idx<256;  idx+=CTHR) sB1[idx]=b1[idx];
    if (tid < 16) ((u64*)sB2)[tid] = pk2(b2[ocb+2*tid], b2[ocb+2*tid+1]);
    for (int idx=tid; idx<=BB; idx+=CTHR) sOffs[idx]=g_offs[idx];
    __syncthreads();

    const int total   = g_total;
    const int nchunks = (total + SEGC - 1)/SEGC;

    for (int c = blockIdx.y; c < nchunks; c += gridDim.y) {
        const int base = c*SEGC;
        const int cnt  = min(SEGC, total - base);

        if (tid < cnt) {
            int n = base + tid, lo=0, hi=BB;
            while (hi-lo>1){ int mid=(lo+hi)>>1; if (sOffs[mid]<=n) lo=mid; else hi=mid; }
            sBi[tid]=lo; sT0[tid]=g_rr[lo] + 5*(n - sOffs[lo]);
        }
        __syncthreads();
        if (tid < cnt*15) {
            int s = tid/15, e = tid - s*15;
            sR[s*15+e] = g_rot[((size_t)sBi[s]*TT + (size_t)sT0[s])*3 + e];
        }
        __syncthreads();

        // conv1
        for (int ch=tid; ch<HH; ch+=CTHR) {
            float w[9];
            #pragma unroll
            for (int i=0;i<9;i++) w[i]=sW1[ch*9+i];
            const float bb = sB1[ch];
            for (int s=0; s<cnt; s++) {
                float* yb = sY + s*YSLAB + ch*8;
                yb[0]=0.0f; yb[6]=0.0f; yb[7]=0.0f;
                const float* xr = sR + s*15;
                #pragma unroll
                for (int p=0;p<5;p++) {
                    float acc = bb;
                    #pragma unroll
                    for (int dt=0;dt<3;dt++) {
                        int t = p+dt-1;
                        if (t>=0 && t<5)
                            acc += w[0*3+dt]*xr[t*3+0] + w[1*3+dt]*xr[t*3+1] + w[2*3+dt]*xr[t*3+2];
                    }
                    yb[1+p] = fmaxf(acc, 0.0f);
                }
            }
        }
        __syncthreads();

        // conv2 + relu + mean (FFMA2, thread = (segment, oc-pair))
        {
            const int s   = tid >> 4;
            const int ocp = tid & 15;
            if (s < cnt) {
                u64 bb = ((u64*)sB2)[ocp];
                u64 a0=bb, a1=bb, a2=bb, a3=bb, a4=bb;
                const float* yrow = sY + s*YSLAB;
                #pragma unroll 2
                for (int j=0;j<HH;j++) {
                    const float4* yv = (const float4*)(yrow + (j<<3));
                    float4 ya = yv[0], yb4 = yv[1];
                    const u64* wp = sW2 + j*48 + ocp;
                    u64 w0 = wp[0], w1v = wp[16], w2v = wp[32];
                    u64 d0=pk2(ya.x,ya.x), d1=pk2(ya.y,ya.y), d2=pk2(ya.z,ya.z), d3=pk2(ya.w,ya.w);
                    u64 d4=pk2(yb4.x,yb4.x), d5=pk2(yb4.y,yb4.y), d6=pk2(yb4.z,yb4.z);
                    fma2(a0,w0,d0); fma2(a0,w1v,d1); fma2(a0,w2v,d2);
                    fma2(a1,w0,d1); fma2(a1,w1v,d2); fma2(a1,w2v,d3);
                    fma2(a2,w0,d2); fma2(a2,w1v,d3); fma2(a2,w2v,d4);
                    fma2(a3,w0,d3); fma2(a3,w1v,d4); fma2(a3,w2v,d5);
                    fma2(a4,w0,d4); fma2(a4,w1v,d5); fma2(a4,w2v,d6);
                }
                float l0,h0,l1,h1,l2,h2,l3,h3,l4,h4;
                up2(a0,l0,h0); up2(a1,l1,h1); up2(a2,l2,h2); up2(a3,l3,h3); up2(a4,l4,h4);
                float m0 = (fmaxf(l0,0.f)+fmaxf(l1,0.f)+fmaxf(l2,0.f)+fmaxf(l3,0.f)+fmaxf(l4,0.f))*0.2f;
                float m1 = (fmaxf(h0,0.f)+fmaxf(h1,0.f)+fmaxf(h2,0.f)+fmaxf(h3,0.f)+fmaxf(h4,0.f))*0.2f;
                *(u64*)&g_ar[(size_t)(base+s)*HH + ocb + 2*ocp] = pk2(m0,m1);
            }
        }
        __syncthreads();
    }
}

// ---------------- kernel 3: gx = ar @ W_ih^T + b_ih ----------------
__global__ __launch_bounds__(256) void k_gx(const float* __restrict__ wih,
                                            const float* __restrict__ bih)
{
    __shared__ float As[64*33];
    __shared__ float Bs[64*33];
    const int total = g_total;
    const int m0 = blockIdx.x*64;
    if (m0 >= total) return;
    const int g0 = blockIdx.y*64;
    const int tid = threadIdx.x;
    const int tr = (tid>>4)*4, tc = (tid&15)*4;
    float acc[4][4] = {};
    for (int kc=0; kc<HH; kc+=32) {
        for (int idx=tid; idx<64*32; idx+=256) {
            int r=idx>>5, kk=idx&31; int m=m0+r;
            As[r*33+kk] = (m<total) ? g_ar[(size_t)m*HH + kc + kk] : 0.0f;
        }
        for (int idx=tid; idx<64*32; idx+=256) {
            int g=idx>>5, kk=idx&31;
            Bs[g*33+kk] = wih[(size_t)(g0+g)*HH + kc + kk];
        }
        __syncthreads();
        #pragma unroll
        for (int kk=0; kk<32; kk++) {
            float a[4], bv[4];
            #pragma unroll
            for (int i=0;i<4;i++) a[i]=As[(tr+i)*33+kk];
            #pragma unroll
            for (int j=0;j<4;j++) bv[j]=Bs[(tc+j)*33+kk];
            #pragma unroll
            for (int i=0;i<4;i++)
                #pragma unroll
                for (int j=0;j<4;j++) acc[i][j]+=a[i]*bv[j];
        }
        __syncthreads();
    }
    float bi[4];
    #pragma unroll
    for (int j=0;j<4;j++) bi[j]=bih[g0+tc+j];
    #pragma unroll
    for (int i=0;i<4;i++) {
        int m=m0+tr+i;
        if (m<total)
            #pragma unroll
            for (int j=0;j<4;j++) g_gx[(size_t)m*768 + g0+tc+j] = acc[i][j]+bi[j];
    }
}

// ---------------- kernel 4: GRU (FFMA2, group barriers) ----------------
#define NBLK 128
__global__ __launch_bounds__(128,1) void k_gru(const float* __restrict__ whh,
                                               const float* __restrict__ bhh,
                                               float* __restrict__ out)
{
    extern __shared__ u64 smu[];
    u64* sWd = smu;             // 48 rows (gate*16+ui) x 257 (dup float2)
    u64* shp = smu + 48*257;    // 8 pairs x 257

    const int tid = threadIdx.x;
    const int bg  = blockIdx.x & 7;      // sample group (16 samples = 8 pairs)
    const int ug  = blockIdx.x >> 3;     // unit group (16 units)

    for (int idx=tid; idx<48*256; idx+=128) {
        int row = idx>>8, kk = idx&255;
        int gate = row>>4, uu = row&15;
        float w = whh[(size_t)(gate*HH + ug*16 + uu)*HH + kk];
        sWd[row*257 + kk] = pk2(w,w);
    }

    const int sp = tid>>4;     // 0..7: sample pair within group
    const int ui = tid&15;
    const int u  = ug*16 + ui;
    const float bhr = bhh[u], bhz = bhh[HH+u], bhn = bhh[2*HH+u];
    const int gp  = bg*8 + sp;           // global pair
    const int b0  = 2*gp, b1v = b0+1;
    const int seg0 = g_segs[b0], seg1 = g_segs[b1v];
    const int off0 = g_offs[b0], off1 = g_offs[b1v];
    const int kmax = g_gmax[bg];
    unsigned* barA = &g_barA[bg*32];
    unsigned* barR = &g_barR[bg*32];

    for (int k=0; k<kmax; k++) {
        const int cur = k&1, nxt = cur^1;

        // group barrier: 16 unit-blocks of this sample group
        __syncthreads();
        if (tid==0) {
            __threadfence();
            unsigned t = atomicAdd(barA, 1u);
            unsigned gen = t/16u + 1u;
            if ((t & 15u) == 15u) atomicExch(barR, gen);
            else while (*(volatile unsigned*)barR < gen) { }
        }
        __syncthreads();

        // stage this group's 8 h-pairs (2048 u64, contiguous in g_h)
        for (int idx=tid; idx<8*HH; idx+=128) {
            int p = idx>>8, kk = idx&255;
            shp[p*257+kk] = __ldcg(&g_h[cur][(size_t)bg*8*HH + idx]);
        }
        __syncthreads();

        // prefetch gx (overlaps with FMA loop)
        int v0 = (k<seg0), v1 = (k<seg1);
        size_t r0 = (size_t)(off0 + (v0 ? k : 0));
        size_t r1 = (size_t)(off1 + (v1 ? k : 0));
        float gxr0=__ldg(&g_gx[r0*768+u]), gxz0=__ldg(&g_gx[r0*768+HH+u]), gxn0=__ldg(&g_gx[r0*768+2*HH+u]);
        float gxr1=__ldg(&g_gx[r1*768+u]), gxz1=__ldg(&g_gx[r1*768+HH+u]), gxn1=__ldg(&g_gx[r1*768+2*HH+u]);

        u64 ar=0ull, az=0ull, an=0ull;
        const u64* wr = sWd + ui*257;
        const u64* wz = sWd + (16+ui)*257;
        const u64* wn = sWd + (32+ui)*257;
        const u64* hp = shp + sp*257;
        #pragma unroll 4
        for (int kk=0; kk<HH; kk++) {
            u64 h = hp[kk];
            fma2(ar, wr[kk], h);
            fma2(az, wz[kk], h);
            fma2(an, wn[kk], h);
        }
        float ar0,ar1,az0,az1,an0,an1, h0old,h1old;
        up2(ar,ar0,ar1); up2(az,az0,az1); up2(an,an0,an1);
        up2(hp[u], h0old, h1old);

        float hn0, hn1;
        if (v0) {
            float r = 1.0f/(1.0f+expf(-(gxr0+ar0+bhr)));
            float z = 1.0f/(1.0f+expf(-(gxz0+az0+bhz)));
            float n = tanhf(gxn0 + r*(an0+bhn));
            hn0 = (1.0f-z)*n + z*h0old;
            out[r0*HH+u] = hn0;
        } else hn0 = h0old;
        if (v1) {
            float r = 1.0f/(1.0f+expf(-(gxr1+ar1+bhr)));
            float z = 1.0f/(1.0f+expf(-(gxz1+az1+bhz)));
            float n = tanhf(gxn1 + r*(an1+bhn));
            hn1 = (1.0f-z)*n + z*h1old;
            out[r1*HH+u] = hn1;
        } else hn1 = h1old;
        __stcg(&g_h[nxt][(size_t)gp*HH + u], pk2(hn0,hn1));
    }
}

// ---------------- launch ----------------
extern "C" void kernel_launch(void* const* d_in, const int* in_sizes, int n_in,
                              void* d_out, int out_size)
{
    const float* traj = (const float*)d_in[0];
    const int*   len  = (const int*)  d_in[1];
    const float* c1w  = (const float*)d_in[2];
    const float* c1b  = (const float*)d_in[3];
    const float* c2w  = (const float*)d_in[4];
    const float* c2b  = (const float*)d_in[5];
    const float* wih  = (const float*)d_in[6];
    const float* whh  = (const float*)d_in[7];
    const float* bih  = (const float*)d_in[8];
    const float* bhh  = (const float*)d_in[9];
    float* out = (float*)d_out;

    const int conv_smem = (768*16*2 + SEGC*YSLAB + 2304 + 256 + 32 + 180)*4;
    const int gru_smem  = (48*257 + 8*257)*8;
    cudaFuncSetAttribute(k_conv, cudaFuncAttributeMaxDynamicSharedMemorySize, conv_smem);
    cudaFuncSetAttribute(k_gru,  cudaFuncAttributeMaxDynamicSharedMemorySize, gru_smem);

    k_setup<<<1, 128>>>(traj, len);
    k_rot<<<512, 256>>>(traj);
    k_conv<<<dim3(8, 18), CTHR, conv_smem>>>(c1w, c1b, c2w, c2b);
    k_gx<<<dim3((MAXSEG + 63)/64, 12), 256>>>(wih, bih);
    k_gru<<<NBLK, 128, gru_smem>>>(whh, bhh, out);
}